// round 1
// baseline (speedup 1.0000x reference)
#include <cuda_runtime.h>

#define N_NODES 4096
#define N_EDGES 131072

// ---------------- scratch (device globals: no allocation allowed) ----------
__device__ float g_deg[N_NODES];
__device__ float g_x1[N_NODES * 36];
__device__ float g_x2[N_NODES * 24];
__device__ float g_x3[N_NODES * 5];
__device__ float g_agg[N_NODES * 36];

// ---------------- utility kernels ------------------------------------------
__global__ void zero_kernel(float* __restrict__ p, int n) {
    int i = blockIdx.x * blockDim.x + threadIdx.x;
    if (i < n) p[i] = 0.0f;
}

__global__ void deg_kernel(const int* __restrict__ dst, float* __restrict__ deg) {
    int e = blockIdx.x * blockDim.x + threadIdx.x;
    if (e < N_EDGES) atomicAdd(&deg[dst[e]], 1.0f);
}

// ---------------- edge kernel: msg + scatter --------------------------------
// thread <-> (edge e, output channel o).  msg[e,o] = sum_i x[src,i] * relu(a_e . W[:,i,o] + b[i,o])
// W tile (6*DIN*DOUT + DIN*DOUT floats) staged in shared memory per block.
template <int DIN, int DOUT>
__global__ void __launch_bounds__(256) edge_kernel(
    const float* __restrict__ x, const float* __restrict__ ea,
    const int* __restrict__ src, const int* __restrict__ dst,
    const float* __restrict__ w, const float* __restrict__ b,
    float* __restrict__ agg)
{
    __shared__ float sW[7 * DIN * DOUT];
    {
        float4* s4 = reinterpret_cast<float4*>(sW);
        const float4* w4 = reinterpret_cast<const float4*>(w);
        const float4* b4 = reinterpret_cast<const float4*>(b);
        const int nw4 = (6 * DIN * DOUT) / 4;
        const int nb4 = (DIN * DOUT) / 4;
        for (int i = threadIdx.x; i < nw4; i += blockDim.x) s4[i] = w4[i];
        for (int i = threadIdx.x; i < nb4; i += blockDim.x) s4[nw4 + i] = b4[i];
    }
    __syncthreads();
    const float* sB = sW + 6 * DIN * DOUT;

    int idx = blockIdx.x * 256 + threadIdx.x;
    if (idx >= N_EDGES * DOUT) return;
    int e = idx / DOUT;
    int o = idx - e * DOUT;

    const float a0 = ea[e * 6 + 0];
    const float a1 = ea[e * 6 + 1];
    const float a2 = ea[e * 6 + 2];
    const float a3 = ea[e * 6 + 3];
    const float a4 = ea[e * 6 + 4];
    const float a5 = ea[e * 6 + 5];
    const int s = src[e];
    const float* __restrict__ xs = x + s * DIN;

    float m = 0.0f;
#pragma unroll
    for (int i = 0; i < DIN; i++) {
        float wv = sB[i * DOUT + o];
        wv = fmaf(a0, sW[0 * DIN * DOUT + i * DOUT + o], wv);
        wv = fmaf(a1, sW[1 * DIN * DOUT + i * DOUT + o], wv);
        wv = fmaf(a2, sW[2 * DIN * DOUT + i * DOUT + o], wv);
        wv = fmaf(a3, sW[3 * DIN * DOUT + i * DOUT + o], wv);
        wv = fmaf(a4, sW[4 * DIN * DOUT + i * DOUT + o], wv);
        wv = fmaf(a5, sW[5 * DIN * DOUT + i * DOUT + o], wv);
        wv = fmaxf(wv, 0.0f);
        m = fmaf(xs[i], wv, m);
    }
    atomicAdd(&agg[dst[e] * DOUT + o], m);
}

// ---------------- node kernel: mean + root linear + bias + relu ------------
template <int DIN, int DOUT>
__global__ void __launch_bounds__(256) node_kernel(
    const float* __restrict__ xin, const float* __restrict__ agg,
    const float* __restrict__ deg,
    const float* __restrict__ lin, const float* __restrict__ bias,
    float* __restrict__ xout)
{
    int idx = blockIdx.x * 256 + threadIdx.x;
    if (idx >= N_NODES * DOUT) return;
    int n = idx / DOUT;
    int o = idx - n * DOUT;
    float v = agg[idx] / fmaxf(deg[n], 1.0f) + bias[o];
    const float* __restrict__ xr = xin + n * DIN;
    const float* __restrict__ lr = lin + o * DIN;
#pragma unroll
    for (int i = 0; i < DIN; i++) v = fmaf(xr[i], lr[i], v);
    xout[idx] = fmaxf(v, 0.0f);
}

// ---------------- pairwise abs-diff: cbt[a,b] = sum_f |x[b,f]-x[a,f]| ------
__global__ void __launch_bounds__(256) cbt_kernel(
    const float* __restrict__ x3, float* __restrict__ out)
{
    __shared__ float sa[16 * 5];
    int bcol = blockIdx.x * 256 + threadIdx.x;
    int a0 = blockIdx.y * 16;
    if (threadIdx.x < 80) sa[threadIdx.x] = x3[a0 * 5 + threadIdx.x];
    __syncthreads();

    const float b0 = x3[bcol * 5 + 0];
    const float b1 = x3[bcol * 5 + 1];
    const float b2 = x3[bcol * 5 + 2];
    const float b3 = x3[bcol * 5 + 3];
    const float b4 = x3[bcol * 5 + 4];

#pragma unroll
    for (int j = 0; j < 16; j++) {
        float s = fabsf(b0 - sa[j * 5 + 0])
                + fabsf(b1 - sa[j * 5 + 1])
                + fabsf(b2 - sa[j * 5 + 2])
                + fabsf(b3 - sa[j * 5 + 3])
                + fabsf(b4 - sa[j * 5 + 4]);
        out[(size_t)(a0 + j) * N_NODES + bcol] = s;
    }
}

// ---------------- launcher --------------------------------------------------
extern "C" void kernel_launch(void* const* d_in, const int* in_sizes, int n_in,
                              void* d_out, int out_size)
{
    const float* x0  = (const float*)d_in[0];
    const float* ea  = (const float*)d_in[1];
    const int*   ei  = (const int*)  d_in[2];
    const int*   src = ei;
    const int*   dst = ei + N_EDGES;

    const float* w1  = (const float*)d_in[3];
    const float* bn1 = (const float*)d_in[4];
    const float* l1  = (const float*)d_in[5];
    const float* bi1 = (const float*)d_in[6];
    const float* w2  = (const float*)d_in[7];
    const float* bn2 = (const float*)d_in[8];
    const float* l2  = (const float*)d_in[9];
    const float* bi2 = (const float*)d_in[10];
    const float* w3  = (const float*)d_in[11];
    const float* bn3 = (const float*)d_in[12];
    const float* l3  = (const float*)d_in[13];
    const float* bi3 = (const float*)d_in[14];

    float *deg, *x1, *x2, *x3, *agg;
    cudaGetSymbolAddress((void**)&deg, g_deg);
    cudaGetSymbolAddress((void**)&x1,  g_x1);
    cudaGetSymbolAddress((void**)&x2,  g_x2);
    cudaGetSymbolAddress((void**)&x3,  g_x3);
    cudaGetSymbolAddress((void**)&agg, g_agg);

    float* out = (float*)d_out;

    // degrees
    zero_kernel<<<(N_NODES + 255) / 256, 256>>>(deg, N_NODES);
    deg_kernel<<<(N_EDGES + 255) / 256, 256>>>(dst, deg);

    // ---- layer 1: 1 -> 36 ----
    zero_kernel<<<(N_NODES * 36 + 255) / 256, 256>>>(agg, N_NODES * 36);
    edge_kernel<1, 36><<<(N_EDGES * 36) / 256, 256>>>(x0, ea, src, dst, w1, bn1, agg);
    node_kernel<1, 36><<<(N_NODES * 36) / 256, 256>>>(x0, agg, deg, l1, bi1, x1);

    // ---- layer 2: 36 -> 24 ----
    zero_kernel<<<(N_NODES * 24 + 255) / 256, 256>>>(agg, N_NODES * 24);
    edge_kernel<36, 24><<<(N_EDGES * 24) / 256, 256>>>(x1, ea, src, dst, w2, bn2, agg);
    node_kernel<36, 24><<<(N_NODES * 24) / 256, 256>>>(x1, agg, deg, l2, bi2, x2);

    // ---- layer 3: 24 -> 5 ----
    zero_kernel<<<(N_NODES * 5 + 255) / 256, 256>>>(agg, N_NODES * 5);
    edge_kernel<24, 5><<<(N_EDGES * 5) / 256, 256>>>(x2, ea, src, dst, w3, bn3, agg);
    node_kernel<24, 5><<<(N_NODES * 5) / 256, 256>>>(x2, agg, deg, l3, bi3, x3);

    // ---- pairwise L1 distance matrix ----
    dim3 cgrid(N_NODES / 256, N_NODES / 16);
    cbt_kernel<<<cgrid, 256>>>(x3, out);
}

// round 2
// speedup vs baseline: 1.3382x; 1.3382x over previous
#include <cuda_runtime.h>

#define N_NODES 4096
#define N_EDGES 131072

// ---------------- scratch (device globals) ----------------------------------
__device__ int   g_counts[N_NODES];
__device__ int   g_offsets[N_NODES + 1];
__device__ int   g_cursor[N_NODES];
__device__ int   g_perm[N_EDGES];
__device__ float g_x1[N_NODES * 36];
__device__ float g_x2[N_NODES * 24];
__device__ float g_x3[N_NODES * 8];
__device__ float g_msg[N_EDGES * 36];   // reused per layer

// ---------------- counting sort by dst ---------------------------------------
__global__ void zero_counts_kernel(int* __restrict__ c) {
    int i = blockIdx.x * blockDim.x + threadIdx.x;
    if (i < N_NODES) c[i] = 0;
}

__global__ void hist_kernel(const int* __restrict__ dst, int* __restrict__ c) {
    int e = blockIdx.x * blockDim.x + threadIdx.x;
    if (e < N_EDGES) atomicAdd(&c[dst[e]], 1);
}

// single block, 1024 threads, 4 elems each -> exclusive scan of 4096 counts
__global__ void scan_kernel(const int* __restrict__ c,
                            int* __restrict__ off, int* __restrict__ cur) {
    __shared__ int s[1024];
    int t = threadIdx.x;
    int c0 = c[4 * t], c1 = c[4 * t + 1], c2 = c[4 * t + 2], c3 = c[4 * t + 3];
    int sum = c0 + c1 + c2 + c3;
    s[t] = sum;
    __syncthreads();
    for (int d = 1; d < 1024; d <<= 1) {
        int v = (t >= d) ? s[t - d] : 0;
        __syncthreads();
        s[t] += v;
        __syncthreads();
    }
    int base = (t > 0) ? s[t - 1] : 0;
    off[4 * t] = base;          cur[4 * t] = base;
    off[4 * t + 1] = base + c0; cur[4 * t + 1] = base + c0;
    off[4 * t + 2] = base + c0 + c1; cur[4 * t + 2] = base + c0 + c1;
    off[4 * t + 3] = base + c0 + c1 + c2; cur[4 * t + 3] = base + c0 + c1 + c2;
    if (t == 1023) off[N_NODES] = s[1023];
}

__global__ void scatter_kernel(const int* __restrict__ dst,
                               int* __restrict__ cur, int* __restrict__ perm) {
    int e = blockIdx.x * blockDim.x + threadIdx.x;
    if (e < N_EDGES) {
        int p = atomicAdd(&cur[dst[e]], 1);
        perm[p] = e;
    }
}

// ---------------- edge kernels: thread = edge, W via broadcast LDS.128 -------
// msg[e,o] = sum_i x[src,i] * relu(sum_v a_v W[v,i,o] + b[i,o])
template <int DIN, int DOUT>
__global__ void __launch_bounds__(256) edge_kernel(
    const float* __restrict__ x, const float* __restrict__ ea,
    const int* __restrict__ src,
    const float* __restrict__ w, const float* __restrict__ b,
    float* __restrict__ msg)
{
    __shared__ float sW[7 * DIN * DOUT];
    {
        float4* s4 = reinterpret_cast<float4*>(sW);
        const float4* w4 = reinterpret_cast<const float4*>(w);
        const float4* b4 = reinterpret_cast<const float4*>(b);
        const int nw4 = (6 * DIN * DOUT) / 4;
        const int nb4 = (DIN * DOUT) / 4;
        for (int i = threadIdx.x; i < nw4; i += blockDim.x) s4[i] = w4[i];
        for (int i = threadIdx.x; i < nb4; i += blockDim.x) s4[nw4 + i] = b4[i];
    }
    __syncthreads();
    const float4* sW4 = reinterpret_cast<const float4*>(sW);
    const float4* sB4 = reinterpret_cast<const float4*>(sW + 6 * DIN * DOUT);

    int e = blockIdx.x * 256 + threadIdx.x;

    // edge attributes (6 floats, 8B-aligned)
    const float2* ea2 = reinterpret_cast<const float2*>(ea + e * 6);
    float2 p0 = ea2[0], p1 = ea2[1], p2 = ea2[2];
    const float a0 = p0.x, a1 = p0.y, a2 = p1.x, a3 = p1.y, a4 = p2.x, a5 = p2.y;

    const int s = src[e];
    const float* __restrict__ xs = x + s * DIN;

    float acc[DOUT];
#pragma unroll
    for (int o = 0; o < DOUT; o++) acc[o] = 0.0f;

    static_assert(DOUT % 4 == 0, "DOUT multiple of 4");
#pragma unroll
    for (int i = 0; i < DIN; i++) {
        const float xi = xs[i];
#pragma unroll
        for (int o4 = 0; o4 < DOUT / 4; o4++) {
            float4 wb = sB4[(i * DOUT) / 4 + o4];
            float4 w0 = sW4[(0 * DIN * DOUT + i * DOUT) / 4 + o4];
            float4 w1 = sW4[(1 * DIN * DOUT + i * DOUT) / 4 + o4];
            float4 w2 = sW4[(2 * DIN * DOUT + i * DOUT) / 4 + o4];
            float4 w3 = sW4[(3 * DIN * DOUT + i * DOUT) / 4 + o4];
            float4 w4v = sW4[(4 * DIN * DOUT + i * DOUT) / 4 + o4];
            float4 w5 = sW4[(5 * DIN * DOUT + i * DOUT) / 4 + o4];
            float v;
            v = wb.x; v = fmaf(a0, w0.x, v); v = fmaf(a1, w1.x, v); v = fmaf(a2, w2.x, v);
            v = fmaf(a3, w3.x, v); v = fmaf(a4, w4v.x, v); v = fmaf(a5, w5.x, v);
            acc[o4 * 4 + 0] = fmaf(xi, fmaxf(v, 0.0f), acc[o4 * 4 + 0]);
            v = wb.y; v = fmaf(a0, w0.y, v); v = fmaf(a1, w1.y, v); v = fmaf(a2, w2.y, v);
            v = fmaf(a3, w3.y, v); v = fmaf(a4, w4v.y, v); v = fmaf(a5, w5.y, v);
            acc[o4 * 4 + 1] = fmaf(xi, fmaxf(v, 0.0f), acc[o4 * 4 + 1]);
            v = wb.z; v = fmaf(a0, w0.z, v); v = fmaf(a1, w1.z, v); v = fmaf(a2, w2.z, v);
            v = fmaf(a3, w3.z, v); v = fmaf(a4, w4v.z, v); v = fmaf(a5, w5.z, v);
            acc[o4 * 4 + 2] = fmaf(xi, fmaxf(v, 0.0f), acc[o4 * 4 + 2]);
            v = wb.w; v = fmaf(a0, w0.w, v); v = fmaf(a1, w1.w, v); v = fmaf(a2, w2.w, v);
            v = fmaf(a3, w3.w, v); v = fmaf(a4, w4v.w, v); v = fmaf(a5, w5.w, v);
            acc[o4 * 4 + 3] = fmaf(xi, fmaxf(v, 0.0f), acc[o4 * 4 + 3]);
        }
    }

    float4* m4 = reinterpret_cast<float4*>(msg + (size_t)e * DOUT);
#pragma unroll
    for (int o4 = 0; o4 < DOUT / 4; o4++) {
        float4 r;
        r.x = acc[o4 * 4 + 0]; r.y = acc[o4 * 4 + 1];
        r.z = acc[o4 * 4 + 2]; r.w = acc[o4 * 4 + 3];
        m4[o4] = r;
    }
}

// layer 3 variant: DOUT=5 (scalar shared loads/stores)
__global__ void __launch_bounds__(256) edge_kernel_l3(
    const float* __restrict__ x, const float* __restrict__ ea,
    const int* __restrict__ src,
    const float* __restrict__ w, const float* __restrict__ b,
    float* __restrict__ msg)
{
    const int DIN = 24, DOUT = 5;
    __shared__ float sW[7 * DIN * DOUT];
    {
        float4* s4 = reinterpret_cast<float4*>(sW);
        const float4* w4 = reinterpret_cast<const float4*>(w);
        const float4* b4 = reinterpret_cast<const float4*>(b);
        for (int i = threadIdx.x; i < (6 * DIN * DOUT) / 4; i += blockDim.x) s4[i] = w4[i];
        for (int i = threadIdx.x; i < (DIN * DOUT) / 4; i += blockDim.x)
            s4[(6 * DIN * DOUT) / 4 + i] = b4[i];
    }
    __syncthreads();
    const float* sB = sW + 6 * DIN * DOUT;

    int e = blockIdx.x * 256 + threadIdx.x;
    const float2* ea2 = reinterpret_cast<const float2*>(ea + e * 6);
    float2 p0 = ea2[0], p1 = ea2[1], p2 = ea2[2];
    const float a0 = p0.x, a1 = p0.y, a2 = p1.x, a3 = p1.y, a4 = p2.x, a5 = p2.y;
    const int s = src[e];
    const float* __restrict__ xs = x + s * DIN;

    float acc[DOUT];
#pragma unroll
    for (int o = 0; o < DOUT; o++) acc[o] = 0.0f;
#pragma unroll
    for (int i = 0; i < DIN; i++) {
        const float xi = xs[i];
#pragma unroll
        for (int o = 0; o < DOUT; o++) {
            float v = sB[i * DOUT + o];
            v = fmaf(a0, sW[0 * DIN * DOUT + i * DOUT + o], v);
            v = fmaf(a1, sW[1 * DIN * DOUT + i * DOUT + o], v);
            v = fmaf(a2, sW[2 * DIN * DOUT + i * DOUT + o], v);
            v = fmaf(a3, sW[3 * DIN * DOUT + i * DOUT + o], v);
            v = fmaf(a4, sW[4 * DIN * DOUT + i * DOUT + o], v);
            v = fmaf(a5, sW[5 * DIN * DOUT + i * DOUT + o], v);
            acc[o] = fmaf(xi, fmaxf(v, 0.0f), acc[o]);
        }
    }
#pragma unroll
    for (int o = 0; o < DOUT; o++) msg[(size_t)e * DOUT + o] = acc[o];
}

// ---------------- aggregation: block per node, CSR gather + root + relu ------
template <int DIN, int DOUT>
__global__ void __launch_bounds__(64) agg_kernel(
    const float* __restrict__ msg, const int* __restrict__ perm,
    const int* __restrict__ off,
    const float* __restrict__ xin, const float* __restrict__ lin,
    const float* __restrict__ bias, float* __restrict__ xout)
{
    int n = blockIdx.x;
    int o = threadIdx.x;
    if (o >= DOUT) return;
    int s = off[n], epos = off[n + 1];
    float acc = 0.0f;
    for (int j = s; j < epos; j++) {
        int e = perm[j];
        acc += msg[(size_t)e * DOUT + o];
    }
    float deg = fmaxf((float)(epos - s), 1.0f);
    float v = acc / deg + bias[o];
    const float* __restrict__ xr = xin + n * DIN;
    const float* __restrict__ lr = lin + o * DIN;
#pragma unroll
    for (int i = 0; i < DIN; i++) v = fmaf(xr[i], lr[i], v);
    xout[n * DOUT + o] = fmaxf(v, 0.0f);
}

// ---------------- pairwise abs-diff ------------------------------------------
__global__ void __launch_bounds__(256) cbt_kernel(
    const float* __restrict__ x3, float* __restrict__ out)
{
    __shared__ float sa[16 * 5];
    int bcol = blockIdx.x * 256 + threadIdx.x;
    int a0 = blockIdx.y * 16;
    if (threadIdx.x < 80) sa[threadIdx.x] = x3[(a0 * 5 / 5) * 5 + threadIdx.x];
    __syncthreads();

    const float b0 = x3[bcol * 5 + 0];
    const float b1 = x3[bcol * 5 + 1];
    const float b2 = x3[bcol * 5 + 2];
    const float b3 = x3[bcol * 5 + 3];
    const float b4 = x3[bcol * 5 + 4];

#pragma unroll
    for (int j = 0; j < 16; j++) {
        float s = fabsf(b0 - sa[j * 5 + 0])
                + fabsf(b1 - sa[j * 5 + 1])
                + fabsf(b2 - sa[j * 5 + 2])
                + fabsf(b3 - sa[j * 5 + 3])
                + fabsf(b4 - sa[j * 5 + 4]);
        out[(size_t)(a0 + j) * N_NODES + bcol] = s;
    }
}

// ---------------- launcher ----------------------------------------------------
extern "C" void kernel_launch(void* const* d_in, const int* in_sizes, int n_in,
                              void* d_out, int out_size)
{
    const float* x0  = (const float*)d_in[0];
    const float* ea  = (const float*)d_in[1];
    const int*   ei  = (const int*)  d_in[2];
    const int*   src = ei;
    const int*   dst = ei + N_EDGES;

    const float* w1  = (const float*)d_in[3];
    const float* bn1 = (const float*)d_in[4];
    const float* l1  = (const float*)d_in[5];
    const float* bi1 = (const float*)d_in[6];
    const float* w2  = (const float*)d_in[7];
    const float* bn2 = (const float*)d_in[8];
    const float* l2  = (const float*)d_in[9];
    const float* bi2 = (const float*)d_in[10];
    const float* w3  = (const float*)d_in[11];
    const float* bn3 = (const float*)d_in[12];
    const float* l3  = (const float*)d_in[13];
    const float* bi3 = (const float*)d_in[14];

    int *counts, *offs, *cur, *perm;
    float *x1, *x2, *x3, *msg;
    cudaGetSymbolAddress((void**)&counts, g_counts);
    cudaGetSymbolAddress((void**)&offs,   g_offsets);
    cudaGetSymbolAddress((void**)&cur,    g_cursor);
    cudaGetSymbolAddress((void**)&perm,   g_perm);
    cudaGetSymbolAddress((void**)&x1,     g_x1);
    cudaGetSymbolAddress((void**)&x2,     g_x2);
    cudaGetSymbolAddress((void**)&x3,     g_x3);
    cudaGetSymbolAddress((void**)&msg,    g_msg);

    float* out = (float*)d_out;

    // counting sort of edges by dst
    zero_counts_kernel<<<N_NODES / 256, 256>>>(counts);
    hist_kernel<<<N_EDGES / 256, 256>>>(dst, counts);
    scan_kernel<<<1, 1024>>>(counts, offs, cur);
    scatter_kernel<<<N_EDGES / 256, 256>>>(dst, cur, perm);

    // layer 1: 1 -> 36
    edge_kernel<1, 36><<<N_EDGES / 256, 256>>>(x0, ea, src, w1, bn1, msg);
    agg_kernel<1, 36><<<N_NODES, 64>>>(msg, perm, offs, x0, l1, bi1, x1);

    // layer 2: 36 -> 24
    edge_kernel<36, 24><<<N_EDGES / 256, 256>>>(x1, ea, src, w2, bn2, msg);
    agg_kernel<36, 24><<<N_NODES, 64>>>(msg, perm, offs, x1, l2, bi2, x2);

    // layer 3: 24 -> 5
    edge_kernel_l3<<<N_EDGES / 256, 256>>>(x2, ea, src, w3, bn3, msg);
    agg_kernel<24, 5><<<N_NODES, 64>>>(msg, perm, offs, x2, l3, bi3, x3);

    // pairwise L1 distance matrix
    dim3 cgrid(N_NODES / 256, N_NODES / 16);
    cbt_kernel<<<cgrid, 256>>>(x3, out);
}